// round 1
// baseline (speedup 1.0000x reference)
#include <cuda_runtime.h>

// Problem constants (fixed by the reference)
#define N_SAE  128
#define D_DATA 128
#define D_DICT 512
#define BATCH  1024
#define CAP    64     // max tokens routed to one expert (mean 16, Poisson tail << CAP)
#define CHUNK  8      // tokens per compute CTA

// Device-side scratch for the expert -> (token, gate) lists
__device__ int   g_cnt[N_SAE];
__device__ int   g_tok[N_SAE * CAP];
__device__ float g_gv [N_SAE * CAP];

// ---------------------------------------------------------------------------
// Kernel 0: zero output + counters
// ---------------------------------------------------------------------------
__global__ void k_zero(float* __restrict__ out) {
    int i = blockIdx.x * blockDim.x + threadIdx.x;
    if (i < BATCH * D_DATA) out[i] = 0.0f;
    if (i < N_SAE) g_cnt[i] = 0;
}

// ---------------------------------------------------------------------------
// Kernel 1: build per-expert token lists from the dense gate [B, N_SAE]
// One block per token, one thread per expert slot. Coalesced gate reads.
// ---------------------------------------------------------------------------
__global__ void k_build(const float* __restrict__ gate) {
    int b = blockIdx.x;
    int e = threadIdx.x;
    float v = gate[b * N_SAE + e];
    if (v != 0.0f) {
        int p = atomicAdd(&g_cnt[e], 1);
        if (p < CAP) {
            g_tok[e * CAP + p] = b;
            g_gv [e * CAP + p] = v;
        }
    }
}

// ---------------------------------------------------------------------------
// Kernel 2: fused encode -> relu -> gate -> decode -> scatter-add
// grid = (N_SAE, CAP/CHUNK); block = 512 threads.
//   Encode : thread t owns dict unit e=t; accumulates 8 tokens over d.
//            W_enc[d*512+e] reads are fully coalesced; x broadcast from smem.
//   Decode : group g=t>>7 owns e in [g*128,(g+1)*128); thread owns output d=t&127
//            for all 8 tokens; acts broadcast from smem (float4); partial sums
//            reduced across the 4 groups through smem; coalesced atomicAdd out.
// ---------------------------------------------------------------------------
__global__ void __launch_bounds__(512, 2)
k_compute(const float* __restrict__ x,
          const float* __restrict__ Wenc,
          const float* __restrict__ Wdec,
          const float* __restrict__ benc,
          const float* __restrict__ bdec,
          float* __restrict__ out) {
    int s = blockIdx.x;
    int n = g_cnt[s];
    if (n > CAP) n = CAP;
    int t0 = blockIdx.y * CHUNK;
    if (t0 >= n) return;
    int m = n - t0; if (m > CHUNK) m = CHUNK;

    __shared__ float xs[D_DATA][CHUNK];     // x transposed: xs[d][j]          (4 KB)
    __shared__ float acts[D_DICT][CHUNK];   // gated post-relu activations     (16 KB)
    __shared__ float part[4][D_DATA][CHUNK];// decode partials per e-group     (16 KB)
    __shared__ float gs[CHUNK];
    __shared__ int   bs[CHUNK];

    int tid = threadIdx.x;
    if (tid < CHUNK) {
        int j = tid;
        if (j < m) {
            bs[j] = g_tok[s * CAP + t0 + j];
            gs[j] = g_gv [s * CAP + t0 + j];
        } else {
            bs[j] = 0;
            gs[j] = 0.0f;
        }
    }
    __syncthreads();

    // Load the chunk's x rows, transposed into smem (coalesced over d).
    for (int i = tid; i < D_DATA * CHUNK; i += 512) {
        int j = i >> 7;        // i / 128
        int d = i & 127;       // i % 128
        xs[d][j] = (j < m) ? x[bs[j] * D_DATA + d] : 0.0f;
    }
    __syncthreads();

    // ---------------- Encode ----------------
    {
        int e = tid;  // 512 threads == D_DICT
        float acc[CHUNK];
        float b = benc[s * D_DICT + e];
        #pragma unroll
        for (int j = 0; j < CHUNK; j++) acc[j] = b;

        const float* W = Wenc + (size_t)s * D_DATA * D_DICT + e;
        #pragma unroll 4
        for (int d = 0; d < D_DATA; d++) {
            float w = __ldg(W + d * D_DICT);
            const float4* xv = (const float4*)xs[d];
            float4 a = xv[0];
            float4 c = xv[1];
            acc[0] = fmaf(a.x, w, acc[0]);
            acc[1] = fmaf(a.y, w, acc[1]);
            acc[2] = fmaf(a.z, w, acc[2]);
            acc[3] = fmaf(a.w, w, acc[3]);
            acc[4] = fmaf(c.x, w, acc[4]);
            acc[5] = fmaf(c.y, w, acc[5]);
            acc[6] = fmaf(c.z, w, acc[6]);
            acc[7] = fmaf(c.w, w, acc[7]);
        }
        #pragma unroll
        for (int j = 0; j < CHUNK; j++)
            acts[e][j] = gs[j] * fmaxf(acc[j], 0.0f);
    }
    __syncthreads();

    // ---------------- Decode ----------------
    {
        int g = tid >> 7;      // e-group 0..3
        int d = tid & 127;     // output dim
        float o[CHUNK];
        #pragma unroll
        for (int j = 0; j < CHUNK; j++) o[j] = 0.0f;

        const float* W = Wdec + (size_t)s * D_DICT * D_DATA + (size_t)g * 128 * D_DATA + d;
        const float (*A)[CHUNK] = &acts[g * 128];
        #pragma unroll 4
        for (int e = 0; e < 128; e++) {
            float w = __ldg(W + e * D_DATA);
            const float4* av = (const float4*)A[e];
            float4 a = av[0];
            float4 c = av[1];
            o[0] = fmaf(a.x, w, o[0]);
            o[1] = fmaf(a.y, w, o[1]);
            o[2] = fmaf(a.z, w, o[2]);
            o[3] = fmaf(a.w, w, o[3]);
            o[4] = fmaf(c.x, w, o[4]);
            o[5] = fmaf(c.y, w, o[5]);
            o[6] = fmaf(c.z, w, o[6]);
            o[7] = fmaf(c.w, w, o[7]);
        }
        #pragma unroll
        for (int j = 0; j < CHUNK; j++) part[g][d][j] = o[j];
    }
    __syncthreads();

    // Reduce the 4 e-group partials + b_dec, scatter-add into the output.
    // i = j*128 + d so each warp's atomics hit 32 consecutive floats.
    for (int i = tid; i < D_DATA * CHUNK; i += 512) {
        int j = i >> 7;
        int d = i & 127;
        if (j < m) {
            float v = part[0][d][j] + part[1][d][j] + part[2][d][j] + part[3][d][j]
                    + bdec[s * D_DATA + d];
            atomicAdd(&out[bs[j] * D_DATA + d], v);
        }
    }
}

// ---------------------------------------------------------------------------
// Launch
// Inputs (metadata order): x, gate, W_enc, W_dec, b_enc, b_dec, k
// ---------------------------------------------------------------------------
extern "C" void kernel_launch(void* const* d_in, const int* in_sizes, int n_in,
                              void* d_out, int out_size) {
    const float* x    = (const float*)d_in[0];
    const float* gate = (const float*)d_in[1];
    const float* Wenc = (const float*)d_in[2];
    const float* Wdec = (const float*)d_in[3];
    const float* benc = (const float*)d_in[4];
    const float* bdec = (const float*)d_in[5];
    float* out = (float*)d_out;

    k_zero<<<(BATCH * D_DATA + 255) / 256, 256>>>(out);
    k_build<<<BATCH, N_SAE>>>(gate);
    dim3 grid(N_SAE, CAP / CHUNK);
    k_compute<<<grid, 512>>>(x, Wenc, Wdec, benc, bdec, out);
}

// round 2
// speedup vs baseline: 1.2742x; 1.2742x over previous
#include <cuda_runtime.h>

// Problem constants (fixed by the reference)
#define N_SAE  128
#define D_DATA 128
#define D_DICT 512
#define BATCH  1024
#define CAP    64     // max tokens per expert (mean 16; overflow prob ~0)
#define CHUNK  8      // tokens per compute CTA

typedef unsigned long long u64;

// Device scratch: expert -> pair lists, and per-pair staged decode output.
__device__ int   g_cnt [N_SAE];            // zero-initialized at load; re-zeroed by k_combine
__device__ int   g_pair[N_SAE * CAP];      // pair id = token*2 + j
__device__ float g_gv  [N_SAE * CAP];
__device__ float g_stage[BATCH * 2 * D_DATA];  // per-pair decode output (1 MB)

// ---------------- f32x2 packed helpers (sm_103a) ----------------
__device__ __forceinline__ u64 pk(float lo, float hi) {
    u64 r; asm("mov.b64 %0,{%1,%2};" : "=l"(r) : "f"(lo), "f"(hi)); return r;
}
__device__ __forceinline__ void upk(float& lo, float& hi, u64 v) {
    asm("mov.b64 {%0,%1},%2;" : "=f"(lo), "=f"(hi) : "l"(v));
}
__device__ __forceinline__ u64 fma2(u64 a, u64 b, u64 c) {
    u64 d; asm("fma.rn.f32x2 %0,%1,%2,%3;" : "=l"(d) : "l"(a), "l"(b), "l"(c)); return d;
}
__device__ __forceinline__ u64 add2(u64 a, u64 b) {
    u64 d; asm("add.rn.f32x2 %0,%1,%2;" : "=l"(d) : "l"(a), "l"(b)); return d;
}
__device__ __forceinline__ u64 mul2(u64 a, u64 b) {
    u64 d; asm("mul.rn.f32x2 %0,%1,%2;" : "=l"(d) : "l"(a), "l"(b)); return d;
}
__device__ __forceinline__ u64 relu2(u64 v) {
    float lo, hi; upk(lo, hi, v);
    return pk(fmaxf(lo, 0.0f), fmaxf(hi, 0.0f));
}

// ---------------------------------------------------------------------------
// Kernel 1: build per-expert pair lists. One block per token (128 threads).
// j = rank of this expert among the token's nonzero gates (block-wide prefix).
// pair id = token*2 + j, so k_combine can read stage rows without indirection.
// ---------------------------------------------------------------------------
__global__ void k_build(const float* __restrict__ gate) {
    int b = blockIdx.x, e = threadIdx.x;
    int warp = e >> 5, lane = e & 31;
    float v = gate[b * N_SAE + e];
    bool nz = (v != 0.0f);
    unsigned mask = __ballot_sync(0xffffffffu, nz);
    __shared__ int wc[4];
    if (lane == 0) wc[warp] = __popc(mask);
    __syncthreads();
    if (nz) {
        int j = __popc(mask & ((1u << lane) - 1));
        for (int w = 0; w < warp; w++) j += wc[w];
        int slot = atomicAdd(&g_cnt[e], 1);
        if (slot < CAP) {
            g_pair[e * CAP + slot] = b * 2 + j;
            g_gv [e * CAP + slot] = v;
        }
    }
}

// ---------------------------------------------------------------------------
// Kernel 2: fused encode -> relu -> gate -> decode, staged per-pair output.
// grid = (N_SAE, CAP/CHUNK), 512 threads, all math in packed f32x2.
//   Encode: thread owns e = {2ep, 2ep+1} (LDG.64 weights), 4 tokens (half).
//   Decode: thread owns d = {2dp, 2dp+1}, 4 tokens, 1/4 of the e range;
//           4-way partial reduce through smem in packed form.
// ---------------------------------------------------------------------------
__global__ void __launch_bounds__(512, 2)
k_compute(const float* __restrict__ x,
          const float* __restrict__ Wenc,
          const float* __restrict__ Wdec,
          const float* __restrict__ benc,
          const float* __restrict__ bdec) {
    int s = blockIdx.x;
    int n = g_cnt[s]; if (n > CAP) n = CAP;
    int t0 = blockIdx.y * CHUNK;
    if (t0 >= n) return;
    int m = n - t0; if (m > CHUNK) m = CHUNK;

    __shared__ __align__(16) float xs[D_DATA][CHUNK];   // x transposed        (4 KB)
    __shared__ u64 acts[D_DICT][6];                     // [0..3] used, padded (24 KB)
    __shared__ u64 part[4][4][D_DATA];                  // decode partials     (16 KB)
    __shared__ u64 gsp[4];                              // packed gate pairs
    __shared__ int pr[CHUNK];                           // pair ids

    int tid = threadIdx.x;
    if (tid < CHUNK) {
        int j = tid;
        int pair = 0; float gv = 0.0f;
        if (j < m) { pair = g_pair[s * CAP + t0 + j]; gv = g_gv[s * CAP + t0 + j]; }
        pr[j] = pair;
        ((float*)gsp)[j] = gv;   // lo = even token, hi = odd token (LE layout)
    }
    __syncthreads();

    // Load chunk x rows, transposed (coalesced over d); pad tokens -> 0.
    for (int i = tid; i < D_DATA * CHUNK; i += 512) {
        int j = i >> 7, d = i & 127;
        xs[d][j] = (j < m) ? x[(pr[j] >> 1) * D_DATA + d] : 0.0f;
    }
    __syncthreads();

    // ---------------- Encode ----------------
    {
        int ep = tid & 255;       // e = 2ep, 2ep+1
        int th = tid >> 8;        // tokens 4th .. 4th+3
        const float2* W = (const float2*)(Wenc + (size_t)s * D_DATA * D_DICT) + ep;
        float2 be = ((const float2*)(benc + (size_t)s * D_DICT))[ep];
        u64 a00 = pk(be.x, be.x), a01 = a00;   // e=2ep,   token pairs {0,1}
        u64 a10 = pk(be.y, be.y), a11 = a10;   // e=2ep+1
        #pragma unroll 8
        for (int d = 0; d < D_DATA; d++) {
            float2 w = __ldg(W + d * (D_DICT / 2));
            u64 w0 = pk(w.x, w.x), w1 = pk(w.y, w.y);
            ulonglong2 xp = ((const ulonglong2*)xs[d])[th];  // 4 tokens as 2 pairs
            a00 = fma2(xp.x, w0, a00);
            a01 = fma2(xp.y, w0, a01);
            a10 = fma2(xp.x, w1, a10);
            a11 = fma2(xp.y, w1, a11);
        }
        u64 g0 = gsp[2 * th], g1 = gsp[2 * th + 1];
        acts[2 * ep    ][2 * th    ] = mul2(relu2(a00), g0);
        acts[2 * ep    ][2 * th + 1] = mul2(relu2(a01), g1);
        acts[2 * ep + 1][2 * th    ] = mul2(relu2(a10), g0);
        acts[2 * ep + 1][2 * th + 1] = mul2(relu2(a11), g1);
    }
    __syncthreads();

    // ---------------- Decode ----------------
    {
        int dp = tid & 63;         // d = 2dp, 2dp+1
        int th = (tid >> 6) & 1;   // tokens 4th .. 4th+3
        int g  = tid >> 7;         // e-group 0..3: e in [128g, 128g+128)
        const float2* W = (const float2*)(Wdec + (size_t)s * D_DICT * D_DATA) + dp;
        u64 a00 = 0, a01 = 0, a10 = 0, a11 = 0;
        int e0 = g * 128;
        #pragma unroll 8
        for (int ee = 0; ee < 128; ee++) {
            int e = e0 + ee;
            float2 w = __ldg(W + e * (D_DATA / 2));
            u64 w0 = pk(w.x, w.x), w1 = pk(w.y, w.y);
            ulonglong2 ap = ((const ulonglong2*)acts[e])[th];
            a00 = fma2(ap.x, w0, a00);
            a01 = fma2(ap.y, w0, a01);
            a10 = fma2(ap.x, w1, a10);
            a11 = fma2(ap.y, w1, a11);
        }
        part[g][2 * th    ][2 * dp    ] = a00;
        part[g][2 * th + 1][2 * dp    ] = a01;
        part[g][2 * th    ][2 * dp + 1] = a10;
        part[g][2 * th + 1][2 * dp + 1] = a11;
    }
    __syncthreads();

    // Reduce 4 e-group partials (packed), add b_dec, write per-pair stage rows.
    {
        int d  = tid & 127;
        int tp = tid >> 7;         // token pair 0..3 -> tokens 2tp, 2tp+1
        u64 sum = part[0][tp][d];
        #pragma unroll
        for (int g = 1; g < 4; g++) sum = add2(sum, part[g][tp][d]);
        float lo, hi; upk(lo, hi, sum);
        float bd = bdec[s * D_DATA + d];
        int j0 = 2 * tp, j1 = 2 * tp + 1;
        if (j0 < m) g_stage[(size_t)pr[j0] * D_DATA + d] = lo + bd;
        if (j1 < m) g_stage[(size_t)pr[j1] * D_DATA + d] = hi + bd;
    }
}

// ---------------------------------------------------------------------------
// Kernel 3: combine the K=2 staged rows per token into the output (float4),
// and re-zero the expert counters for the next graph replay.
// ---------------------------------------------------------------------------
__global__ void k_combine(float* __restrict__ out) {
    int i = blockIdx.x * 256 + threadIdx.x;      // 0..32767 float4 units
    const float4* st = (const float4*)g_stage;
    int b = i >> 5, d4 = i & 31;
    float4 a = st[b * 64 + d4];
    float4 c = st[b * 64 + 32 + d4];
    float4 r;
    r.x = a.x + c.x; r.y = a.y + c.y; r.z = a.z + c.z; r.w = a.w + c.w;
    ((float4*)out)[i] = r;
    if (i < N_SAE) g_cnt[i] = 0;
}

// ---------------------------------------------------------------------------
// Launch. Inputs (metadata order): x, gate, W_enc, W_dec, b_enc, b_dec, k
// ---------------------------------------------------------------------------
extern "C" void kernel_launch(void* const* d_in, const int* in_sizes, int n_in,
                              void* d_out, int out_size) {
    const float* x    = (const float*)d_in[0];
    const float* gate = (const float*)d_in[1];
    const float* Wenc = (const float*)d_in[2];
    const float* Wdec = (const float*)d_in[3];
    const float* benc = (const float*)d_in[4];
    const float* bdec = (const float*)d_in[5];
    float* out = (float*)d_out;

    k_build<<<BATCH, N_SAE>>>(gate);
    dim3 grid(N_SAE, CAP / CHUNK);
    k_compute<<<grid, 512>>>(x, Wenc, Wdec, benc, bdec);
    k_combine<<<(BATCH * D_DATA / 4) / 256, 256>>>(out);
}